// round 1
// baseline (speedup 1.0000x reference)
#include <cuda_runtime.h>
#include <cuda_bf16.h>

// ---------------------------------------------------------------------------
// MultitaskLoss: BCE(binary) + BCE(type[B,4]) + CE(source[B,16])
//              + mean(binary_c ^ type_c) + mean(binary_c ^ source_c)
// Pure streaming reduction, ~226 MB in / 4 B out -> HBM-bound.
// Kernel 1: grid-stride fused reduce -> per-block partials (no atomics).
// Kernel 2: double-precision finalize of 1184x5 partials -> scalar.
// ---------------------------------------------------------------------------

#define NBLK 1184          // 148 SMs * 8 — one wave worth of work per block
#define NTHR 256

__device__ float g_part[5 * NBLK];   // [accumulator][block], SoA

// Stable softplus: sp(x) = max(x,0) + log(1 + exp(-|x|)).
// e = exp(-|x|) in (0,1]; __logf(1+e) abs error < 1e-7 when e tiny — harmless.
__device__ __forceinline__ float softplusf(float x) {
    return fmaxf(x, 0.0f) + __logf(1.0f + __expf(-fabsf(x)));
}

__device__ __forceinline__ float pick4(float4 v, int j) {
    // branchless component select (compiles to SELs, no local-memory spill)
    float r = v.x;
    r = (j == 1) ? v.y : r;
    r = (j == 2) ? v.z : r;
    r = (j == 3) ? v.w : r;
    return r;
}

__global__ void __launch_bounds__(NTHR)
mtl_reduce_kernel(const float*  __restrict__ pb,    // [B]    y_pred_binary
                  const float4* __restrict__ pt4,   // [B,4]  y_pred_type
                  const float4* __restrict__ ps4,   // [B,16] y_pred_source (as 4x float4)
                  const float*  __restrict__ tb,    // [B]    y_true_binary
                  const float4* __restrict__ tt4,   // [B,4]  y_true_type
                  const int*    __restrict__ lbl,   // [B]    y_true_source
                  int B)
{
    float s_b = 0.f, s_t = 0.f, s_ce = 0.f, s_ab = 0.f, s_ac = 0.f;

    const int stride = gridDim.x * blockDim.x;
    for (int i = blockIdx.x * blockDim.x + threadIdx.x; i < B; i += stride) {
        // ---- binary BCE: sp(x) - y*x ----
        float xb = pb[i];
        float yb = tb[i];
        s_b += softplusf(xb) - yb * xb;

        // ---- type BCE over 4 logits ----
        float4 xt = pt4[i];
        float4 yt = tt4[i];
        s_t += (softplusf(xt.x) - yt.x * xt.x)
             + (softplusf(xt.y) - yt.y * xt.y)
             + (softplusf(xt.z) - yt.z * xt.z)
             + (softplusf(xt.w) - yt.w * xt.w);
        bool type_c = (xt.x >= 0.f) | (xt.y >= 0.f) | (xt.z >= 0.f) | (xt.w >= 0.f);

        // ---- source CE over 16 logits ----
        float4 a = ps4[4 * i + 0];
        float4 b = ps4[4 * i + 1];
        float4 c = ps4[4 * i + 2];
        float4 d = ps4[4 * i + 3];

        float m = fmaxf(
            fmaxf(fmaxf(fmaxf(a.x, a.y), fmaxf(a.z, a.w)),
                  fmaxf(fmaxf(b.x, b.y), fmaxf(b.z, b.w))),
            fmaxf(fmaxf(fmaxf(c.x, c.y), fmaxf(c.z, c.w)),
                  fmaxf(fmaxf(d.x, d.y), fmaxf(d.z, d.w))));

        float se = __expf(a.x - m) + __expf(a.y - m) + __expf(a.z - m) + __expf(a.w - m)
                 + __expf(b.x - m) + __expf(b.y - m) + __expf(b.z - m) + __expf(b.w - m)
                 + __expf(c.x - m) + __expf(c.y - m) + __expf(c.z - m) + __expf(c.w - m)
                 + __expf(d.x - m) + __expf(d.y - m) + __expf(d.z - m) + __expf(d.w - m);

        int l = lbl[i];
        float4 v = (l < 8) ? ((l < 4) ? a : b) : ((l < 12) ? c : d);
        float xl = pick4(v, l & 3);
        s_ce += m + __logf(se) - xl;

        // ---- consistency bits ----
        bool bc = (xb >= 0.f);            // sigmoid(x) >= 0.5  <=>  x >= 0
        bool sc = (a.x < m);              // argmax > 0 (first-occurrence rule)
        s_ab += (bc != type_c) ? 1.f : 0.f;
        s_ac += (bc != sc)     ? 1.f : 0.f;
    }

    // ---- block reduction: warp shuffle, then smem across warps ----
    #pragma unroll
    for (int o = 16; o; o >>= 1) {
        s_b  += __shfl_down_sync(0xffffffffu, s_b,  o);
        s_t  += __shfl_down_sync(0xffffffffu, s_t,  o);
        s_ce += __shfl_down_sync(0xffffffffu, s_ce, o);
        s_ab += __shfl_down_sync(0xffffffffu, s_ab, o);
        s_ac += __shfl_down_sync(0xffffffffu, s_ac, o);
    }

    __shared__ float sm[5][NTHR / 32];
    int warp = threadIdx.x >> 5;
    int lane = threadIdx.x & 31;
    if (lane == 0) {
        sm[0][warp] = s_b;
        sm[1][warp] = s_t;
        sm[2][warp] = s_ce;
        sm[3][warp] = s_ab;
        sm[4][warp] = s_ac;
    }
    __syncthreads();

    if (threadIdx.x == 0) {
        float t0 = 0.f, t1 = 0.f, t2 = 0.f, t3 = 0.f, t4 = 0.f;
        #pragma unroll
        for (int k = 0; k < NTHR / 32; k++) {
            t0 += sm[0][k]; t1 += sm[1][k]; t2 += sm[2][k];
            t3 += sm[3][k]; t4 += sm[4][k];
        }
        g_part[0 * NBLK + blockIdx.x] = t0;
        g_part[1 * NBLK + blockIdx.x] = t1;
        g_part[2 * NBLK + blockIdx.x] = t2;
        g_part[3 * NBLK + blockIdx.x] = t3;
        g_part[4 * NBLK + blockIdx.x] = t4;
    }
}

__global__ void __launch_bounds__(NTHR)
mtl_finalize_kernel(float* __restrict__ out, int B)
{
    double acc[5] = {0.0, 0.0, 0.0, 0.0, 0.0};
    for (int bidx = threadIdx.x; bidx < NBLK; bidx += blockDim.x) {
        #pragma unroll
        for (int k = 0; k < 5; k++)
            acc[k] += (double)g_part[k * NBLK + bidx];
    }

    #pragma unroll
    for (int o = 16; o; o >>= 1) {
        #pragma unroll
        for (int k = 0; k < 5; k++)
            acc[k] += __shfl_down_sync(0xffffffffu, acc[k], o);
    }

    __shared__ double sm[5][NTHR / 32];
    int warp = threadIdx.x >> 5;
    int lane = threadIdx.x & 31;
    if (lane == 0) {
        #pragma unroll
        for (int k = 0; k < 5; k++) sm[k][warp] = acc[k];
    }
    __syncthreads();

    if (threadIdx.x == 0) {
        double t[5] = {0.0, 0.0, 0.0, 0.0, 0.0};
        #pragma unroll
        for (int w = 0; w < NTHR / 32; w++) {
            #pragma unroll
            for (int k = 0; k < 5; k++) t[k] += sm[k][w];
        }
        double Bd = (double)B;
        double loss = t[0] / Bd            // binary BCE mean
                    + t[1] / (Bd * 4.0)    // type BCE mean over B*T
                    + t[2] / Bd            // CE mean
                    + t[3] / Bd            // cons_ab mean
                    + t[4] / Bd;           // cons_ac mean
        out[0] = (float)loss;
    }
}

extern "C" void kernel_launch(void* const* d_in, const int* in_sizes, int n_in,
                              void* d_out, int out_size)
{
    const float*  pb  = (const float*) d_in[0];   // y_pred_binary  [B]
    const float4* pt4 = (const float4*)d_in[1];   // y_pred_type    [B,4]
    const float4* ps4 = (const float4*)d_in[2];   // y_pred_source  [B,16]
    const float*  tb  = (const float*) d_in[3];   // y_true_binary  [B]
    const float4* tt4 = (const float4*)d_in[4];   // y_true_type    [B,4]
    const int*    lbl = (const int*)   d_in[5];   // y_true_source  [B]
    float* out = (float*)d_out;

    int B = in_sizes[0];

    mtl_reduce_kernel<<<NBLK, NTHR>>>(pb, pt4, ps4, tb, tt4, lbl, B);
    mtl_finalize_kernel<<<1, NTHR>>>(out, B);
}